// round 2
// baseline (speedup 1.0000x reference)
#include <cuda_runtime.h>

// SVConv2d: out[n,o,h,w] = bias[o] + sum_{ci,kh,kw} x[n,ci,h+kh-1,w+kw-1] * W[o,ci,kh,kw,h,w]
// N=8, Cin=Cout=32, K=3, H=W=64. Weight (151 MB) streams once -> DRAM-bound.
// R2: warp spans 32 consecutive w (full 128B weight lines), CPB=2, 512 blocks
// for ~2x occupancy vs R1. smem keeps x traffic off LTS.

#define TW 32
#define TH 4
#define CPB 2

__device__ __forceinline__ unsigned long long pack2(float a, float b) {
    unsigned long long r;
    asm("mov.b64 %0, {%1, %2};" : "=l"(r) : "f"(a), "f"(b));
    return r;
}
__device__ __forceinline__ void fma2(unsigned long long& d, unsigned long long a, unsigned long long b) {
    asm("fma.rn.f32x2 %0, %1, %2, %0;" : "+l"(d) : "l"(a), "l"(b));
}
__device__ __forceinline__ float2 unpack2(unsigned long long v) {
    float x, y;
    asm("mov.b64 {%0, %1}, %2;" : "=f"(x), "=f"(y) : "l"(v));
    return make_float2(x, y);
}

__global__ __launch_bounds__(TW * TH)
void svconv_kernel(const float* __restrict__ x,
                   const float* __restrict__ weight,
                   const float* __restrict__ bias,
                   float* __restrict__ out) {
    constexpr int Cin = 32, Cout = 32, H = 64, W = 64, HW = H * W;
    constexpr int HR = TH + 2, WR = TW + 2;   // halo tile 6 x 34
    constexpr int NSTAGE = 8 * HR * WR;       // 1632 elements per cin

    // Two float4 planes (n0..3 / n4..7). 16B col stride -> conflict-free LDS.128.
    __shared__ float4 xs0[HR][WR];
    __shared__ float4 xs1[HR][WR];

    const int tx = threadIdx.x, ty = threadIdx.y;
    const int tid = ty * TW + tx;
    const int w0 = blockIdx.x * TW;
    const int h0 = blockIdx.y * TH;
    const int c0 = blockIdx.z * CPB;
    const int h = h0 + ty, w = w0 + tx;

    unsigned long long acc[CPB][4];
#pragma unroll
    for (int c = 0; c < CPB; c++)
#pragma unroll
        for (int j = 0; j < 4; j++) acc[c][j] = 0ull;

    // per-thread weight base at (c0, cin=0, k=0, h, w)
    const float* wp = weight + (size_t)c0 * Cin * 9 * HW + h * W + w;

#pragma unroll 1
    for (int cin = 0; cin < Cin; cin++) {
        // ---- stage x halo tile (all 8 n) for this cin ----
#pragma unroll
        for (int i = tid; i < NSTAGE; i += TW * TH) {
            int n = i / (HR * WR);
            int rc = i - n * (HR * WR);
            int r = rc / WR, c = rc - r * WR;
            int gh = h0 + r - 1, gw = w0 + c - 1;
            float v = 0.0f;
            if ((unsigned)gh < (unsigned)H && (unsigned)gw < (unsigned)W)
                v = x[((n * Cin + cin) * H + gh) * W + gw];
            if (n < 4)
                ((float*)&xs0[r][c])[n] = v;
            else
                ((float*)&xs1[r][c])[n - 4] = v;
        }
        __syncthreads();

        const float* wpc = wp + (size_t)cin * 9 * HW;

#pragma unroll
        for (int k = 0; k < 9; k++) {
            const int kh = k / 3, kw = k % 3;
            float4 lo = xs0[ty + kh][tx + kw];
            float4 hi = xs1[ty + kh][tx + kw];
            unsigned long long xq0 = pack2(lo.x, lo.y);
            unsigned long long xq1 = pack2(lo.z, lo.w);
            unsigned long long xq2 = pack2(hi.x, hi.y);
            unsigned long long xq3 = pack2(hi.z, hi.w);
#pragma unroll
            for (int c = 0; c < CPB; c++) {
                // weight used once: stream past L2, keep x resident
                float wv = __ldcs(wpc + c * (Cin * 9 * HW) + k * HW);
                unsigned long long wd = pack2(wv, wv);
                fma2(acc[c][0], wd, xq0);
                fma2(acc[c][1], wd, xq1);
                fma2(acc[c][2], wd, xq2);
                fma2(acc[c][3], wd, xq3);
            }
        }
        __syncthreads();
    }

    // ---- epilogue: add bias, write 8 n x CPB couts (w-coalesced) ----
#pragma unroll
    for (int c = 0; c < CPB; c++) {
        float b = bias[c0 + c];
#pragma unroll
        for (int j = 0; j < 4; j++) {
            float2 v = unpack2(acc[c][j]);
            int n0 = 2 * j, n1 = 2 * j + 1;
            out[((n0 * Cout + (c0 + c)) * H + h) * W + w] = v.x + b;
            out[((n1 * Cout + (c0 + c)) * H + h) * W + w] = v.y + b;
        }
    }
}

extern "C" void kernel_launch(void* const* d_in, const int* in_sizes, int n_in,
                              void* d_out, int out_size) {
    const float* x = (const float*)d_in[0];
    const float* wgt = (const float*)d_in[1];
    const float* bias = (const float*)d_in[2];
    float* out = (float*)d_out;

    dim3 grid(64 / TW, 64 / TH, 32 / CPB);  // 2 x 16 x 16 = 512 blocks
    dim3 block(TW, TH);                     // 128 threads, warp = 32 consecutive w
    svconv_kernel<<<grid, block>>>(x, wgt, bias, out);
}

// round 3
// speedup vs baseline: 1.8696x; 1.8696x over previous
#include <cuda_runtime.h>

// SVConv2d: out[n,o,h,w] = bias[o] + sum_{ci,kh,kw} x[n,ci,h+kh-1,w+kw-1] * W[o,ci,kh,kw,h,w]
// N=8, Cin=Cout=32, K=3, H=W=64. Weight (151 MB) streams once -> DRAM-bound.
// R3: no smem, no barriers. x pre-transposed to (cin,h,w,n8) quads; each warp is an
// independent load stream (L1 catches tap overlap). 2-way cin split for occupancy,
// partials reduced by a second kernel.

typedef unsigned long long ull;

#define HW 4096
#define SPLIT 2

// scratch (allocation-free: __device__ globals)
__device__ float4 g_xt[32 * HW * 2];               // (cin,h,w,n8) : 4 MB
__device__ float g_part[SPLIT * 8 * 32 * HW];      // partial sums : 8 MB

__device__ __forceinline__ ull pack2(float a, float b) {
    ull r; asm("mov.b64 %0, {%1, %2};" : "=l"(r) : "f"(a), "f"(b)); return r;
}
__device__ __forceinline__ void fma2(ull& d, ull a, ull b) {
    asm("fma.rn.f32x2 %0, %1, %2, %0;" : "+l"(d) : "l"(a), "l"(b));
}
__device__ __forceinline__ float2 unpack2(ull v) {
    float x, y; asm("mov.b64 {%0, %1}, %2;" : "=f"(x), "=f"(y) : "l"(v));
    return make_float2(x, y);
}
// predicated 32-byte load of one x quad (8 n values as 4 f32x2), zero if !ok
__device__ __forceinline__ void ldx8(ull& a, ull& b, ull& c, ull& d,
                                     const float4* p, int ok) {
    asm volatile(
        "{\n\t.reg .pred p;\n\t"
        "setp.ne.s32 p, %6, 0;\n\t"
        "mov.u64 %0, 0; mov.u64 %1, 0; mov.u64 %2, 0; mov.u64 %3, 0;\n\t"
        "@p ld.global.nc.v2.u64 {%0, %1}, [%4];\n\t"
        "@p ld.global.nc.v2.u64 {%2, %3}, [%5];\n\t}"
        : "=l"(a), "=l"(b), "=l"(c), "=l"(d)
        : "l"(p), "l"(p + 1), "r"(ok));
}

// ---- kernel 1: transpose x (n,cin,h,w) -> (cin,h,w,n8) ----
__global__ __launch_bounds__(256) void transpose_x(const float* __restrict__ x) {
    int idx = blockIdx.x * 256 + threadIdx.x;      // < 32*4096
    int cin = idx >> 12, pix = idx & 4095;
    float4 lo, hi;
    lo.x = x[(0 * 32 + cin) * HW + pix];
    lo.y = x[(1 * 32 + cin) * HW + pix];
    lo.z = x[(2 * 32 + cin) * HW + pix];
    lo.w = x[(3 * 32 + cin) * HW + pix];
    hi.x = x[(4 * 32 + cin) * HW + pix];
    hi.y = x[(5 * 32 + cin) * HW + pix];
    hi.z = x[(6 * 32 + cin) * HW + pix];
    hi.w = x[(7 * 32 + cin) * HW + pix];
    g_xt[idx * 2] = lo;
    g_xt[idx * 2 + 1] = hi;
}

// ---- kernel 2: main. block (32,4); warp = 32 consecutive w ----
__global__ __launch_bounds__(128) void svconv_main(const float* __restrict__ wt_g) {
    const int lane = threadIdx.x, row = threadIdx.y;
    const int px = blockIdx.x * 32 + lane;
    const int py = blockIdx.y * 4 + row;
    const int c0 = (blockIdx.z & 7) * 4;           // cout group (4 couts)
    const int s = blockIdx.z >> 3;                  // cin half

    ull acc[4][4];
#pragma unroll
    for (int c = 0; c < 4; c++)
#pragma unroll
        for (int j = 0; j < 4; j++) acc[c][j] = 0ull;

    // cin-invariant tap validity + offsets (float4 units)
    int ok[9], xoff[9];
#pragma unroll
    for (int t = 0; t < 9; t++) {
        int dh = t / 3 - 1, dw = t % 3 - 1;
        ok[t] = ((unsigned)(py + dh) < 64u) && ((unsigned)(px + dw) < 64u);
        xoff[t] = (dh * 64 + dw) * 2;
    }

    const float4* xb = g_xt + ((size_t)(s * 16 * 64 + py) * 64 + px) * 2;
    const float* wp = wt_g + (size_t)(c0 * 32 + s * 16) * 9 * HW + py * 64 + px;

#pragma unroll 1
    for (int ci = 0; ci < 16; ci++) {
#pragma unroll
        for (int t = 0; t < 9; t++) {
            ull xq0, xq1, xq2, xq3;
            ldx8(xq0, xq1, xq2, xq3, xb + xoff[t], ok[t]);
#pragma unroll
            for (int c = 0; c < 4; c++) {
                float wv = __ldcs(wp + (size_t)c * (32 * 9 * HW) + t * HW);
                ull wd = pack2(wv, wv);
                fma2(acc[c][0], wd, xq0);
                fma2(acc[c][1], wd, xq1);
                fma2(acc[c][2], wd, xq2);
                fma2(acc[c][3], wd, xq3);
            }
        }
        xb += 64 * 64 * 2;   // next cin
        wp += 9 * HW;
    }

    // write partials (no bias here), coalesced along w
    float* pb = g_part + (size_t)s * (8 * 32 * HW) + (size_t)c0 * HW + py * 64 + px;
#pragma unroll
    for (int c = 0; c < 4; c++)
#pragma unroll
        for (int j = 0; j < 4; j++) {
            float2 v = unpack2(acc[c][j]);
            int n0 = 2 * j, n1 = 2 * j + 1;
            pb[((size_t)n0 * 32 + c) * HW] = v.x;
            pb[((size_t)n1 * 32 + c) * HW] = v.y;
        }
}

// ---- kernel 3: reduce partials + bias ----
__global__ __launch_bounds__(256) void reduce_out(const float* __restrict__ bias,
                                                  float* __restrict__ out) {
    int idx = blockIdx.x * 256 + threadIdx.x;      // < 8*32*4096
    int o = (idx >> 12) & 31;
    out[idx] = g_part[idx] + g_part[idx + 8 * 32 * HW] + bias[o];
}

extern "C" void kernel_launch(void* const* d_in, const int* in_sizes, int n_in,
                              void* d_out, int out_size) {
    const float* x = (const float*)d_in[0];
    const float* wgt = (const float*)d_in[1];
    const float* bias = (const float*)d_in[2];
    float* out = (float*)d_out;

    transpose_x<<<(32 * HW) / 256, 256>>>(x);
    dim3 grid(2, 16, 8 * SPLIT);                   // 512 blocks
    dim3 block(32, 4);                             // 128 threads
    svconv_main<<<grid, block>>>(wgt);
    reduce_out<<<(8 * 32 * HW) / 256, 256>>>(bias, out);
}

// round 4
// speedup vs baseline: 2.0121x; 1.0762x over previous
#include <cuda_runtime.h>

// SVConv2d: out[n,o,h,w] = bias[o] + sum_{ci,kh,kw} x[n,ci,h+kh-1,w+kw-1] * W[o,ci,kh,kw,h,w]
// N=8, Cin=Cout=32, K=3, H=W=64. Weight (151 MB) streams once -> DRAM-bound.
// R4: barrier-free like R3, but CPB=2 + 16 cout groups -> 1024 blocks
// (~28 warps/SM, 2x R3) and half the accumulator registers so ptxas can
// batch more loads per warp. x pre-transposed to (cin,h,w,n8).

typedef unsigned long long ull;

#define HW 4096
#define SPLIT 2
#define CPB 2

// scratch (allocation-free: __device__ globals)
__device__ float4 g_xt[32 * HW * 2];               // (cin,h,w,n8) : 4 MB
__device__ float g_part[SPLIT * 8 * 32 * HW];      // partial sums : 8 MB

__device__ __forceinline__ ull pack2(float a, float b) {
    ull r; asm("mov.b64 %0, {%1, %2};" : "=l"(r) : "f"(a), "f"(b)); return r;
}
__device__ __forceinline__ void fma2(ull& d, ull a, ull b) {
    asm("fma.rn.f32x2 %0, %1, %2, %0;" : "+l"(d) : "l"(a), "l"(b));
}
__device__ __forceinline__ float2 unpack2(ull v) {
    float x, y; asm("mov.b64 {%0, %1}, %2;" : "=f"(x), "=f"(y) : "l"(v));
    return make_float2(x, y);
}
// predicated 32-byte load of one x quad (8 n values as 4 f32x2), zero if !ok
__device__ __forceinline__ void ldx8(ull& a, ull& b, ull& c, ull& d,
                                     const float4* p, int ok) {
    asm volatile(
        "{\n\t.reg .pred p;\n\t"
        "setp.ne.s32 p, %6, 0;\n\t"
        "mov.u64 %0, 0; mov.u64 %1, 0; mov.u64 %2, 0; mov.u64 %3, 0;\n\t"
        "@p ld.global.nc.v2.u64 {%0, %1}, [%4];\n\t"
        "@p ld.global.nc.v2.u64 {%2, %3}, [%5];\n\t}"
        : "=l"(a), "=l"(b), "=l"(c), "=l"(d)
        : "l"(p), "l"(p + 1), "r"(ok));
}

// ---- kernel 1: transpose x (n,cin,h,w) -> (cin,h,w,n8) ----
__global__ __launch_bounds__(256) void transpose_x(const float* __restrict__ x) {
    int idx = blockIdx.x * 256 + threadIdx.x;      // < 32*4096
    int cin = idx >> 12, pix = idx & 4095;
    float4 lo, hi;
    lo.x = x[(0 * 32 + cin) * HW + pix];
    lo.y = x[(1 * 32 + cin) * HW + pix];
    lo.z = x[(2 * 32 + cin) * HW + pix];
    lo.w = x[(3 * 32 + cin) * HW + pix];
    hi.x = x[(4 * 32 + cin) * HW + pix];
    hi.y = x[(5 * 32 + cin) * HW + pix];
    hi.z = x[(6 * 32 + cin) * HW + pix];
    hi.w = x[(7 * 32 + cin) * HW + pix];
    g_xt[idx * 2] = lo;
    g_xt[idx * 2 + 1] = hi;
}

// ---- kernel 2: main. block (32,4); warp = 32 consecutive w; no smem/barriers ----
__global__ __launch_bounds__(128) void svconv_main(const float* __restrict__ wt_g) {
    const int lane = threadIdx.x, row = threadIdx.y;
    const int px = blockIdx.x * 32 + lane;
    const int py = blockIdx.y * 4 + row;
    const int c0 = (blockIdx.z & 15) * CPB;        // cout group (2 couts)
    const int s = blockIdx.z >> 4;                 // cin half

    ull acc[CPB][4];
#pragma unroll
    for (int c = 0; c < CPB; c++)
#pragma unroll
        for (int j = 0; j < 4; j++) acc[c][j] = 0ull;

    // cin-invariant tap validity + offsets (float4 units)
    int ok[9], xoff[9];
#pragma unroll
    for (int t = 0; t < 9; t++) {
        int dh = t / 3 - 1, dw = t % 3 - 1;
        ok[t] = ((unsigned)(py + dh) < 64u) && ((unsigned)(px + dw) < 64u);
        xoff[t] = (dh * 64 + dw) * 2;
    }

    const float4* xb = g_xt + ((size_t)(s * 16 * 64 + py) * 64 + px) * 2;
    const float* wp = wt_g + (size_t)(c0 * 32 + s * 16) * 9 * HW + py * 64 + px;

#pragma unroll 1
    for (int ci = 0; ci < 16; ci++) {
#pragma unroll
        for (int t = 0; t < 9; t++) {
            // issue independent weight loads first, then x loads
            float wv0 = __ldcs(wp + (size_t)0 * (32 * 9 * HW) + t * HW);
            float wv1 = __ldcs(wp + (size_t)1 * (32 * 9 * HW) + t * HW);
            ull xq0, xq1, xq2, xq3;
            ldx8(xq0, xq1, xq2, xq3, xb + xoff[t], ok[t]);
            ull wd0 = pack2(wv0, wv0);
            ull wd1 = pack2(wv1, wv1);
            fma2(acc[0][0], wd0, xq0);
            fma2(acc[0][1], wd0, xq1);
            fma2(acc[0][2], wd0, xq2);
            fma2(acc[0][3], wd0, xq3);
            fma2(acc[1][0], wd1, xq0);
            fma2(acc[1][1], wd1, xq1);
            fma2(acc[1][2], wd1, xq2);
            fma2(acc[1][3], wd1, xq3);
        }
        xb += 64 * 64 * 2;   // next cin
        wp += 9 * HW;
    }

    // write partials (no bias here), coalesced along w
    float* pb = g_part + (size_t)s * (8 * 32 * HW) + (size_t)c0 * HW + py * 64 + px;
#pragma unroll
    for (int c = 0; c < CPB; c++)
#pragma unroll
        for (int j = 0; j < 4; j++) {
            float2 v = unpack2(acc[c][j]);
            int n0 = 2 * j, n1 = 2 * j + 1;
            pb[(((size_t)n0 * 32) + c) * HW] = v.x;
            pb[(((size_t)n1 * 32) + c) * HW] = v.y;
        }
}

// ---- kernel 3: reduce partials + bias ----
__global__ __launch_bounds__(256) void reduce_out(const float* __restrict__ bias,
                                                  float* __restrict__ out) {
    int idx = blockIdx.x * 256 + threadIdx.x;      // < 8*32*4096
    int o = (idx >> 12) & 31;
    out[idx] = g_part[idx] + g_part[idx + 8 * 32 * HW] + bias[o];
}

extern "C" void kernel_launch(void* const* d_in, const int* in_sizes, int n_in,
                              void* d_out, int out_size) {
    const float* x = (const float*)d_in[0];
    const float* wgt = (const float*)d_in[1];
    const float* bias = (const float*)d_in[2];
    float* out = (float*)d_out;

    transpose_x<<<(32 * HW) / 256, 256>>>(x);
    dim3 grid(2, 16, 16 * SPLIT);                  // 1024 blocks
    dim3 block(32, 4);                             // 128 threads
    svconv_main<<<grid, block>>>(wgt);
    reduce_out<<<(8 * 32 * HW) / 256, 256>>>(bias, out);
}

// round 5
// speedup vs baseline: 3.0398x; 1.5108x over previous
#include <cuda_runtime.h>

// SVConv2d: out[n,o,h,w] = bias[o] + sum_{ci,kh,kw} x[n,ci,h+kh-1,w+kw-1] * W[o,ci,kh,kw,h,w]
// N=8, Cin=Cout=32, K=3, H=W=64. Weight (151 MB) streams once -> DRAM-bound.
// R5: zero-padded x planes (cin,66,66) as two float4 planes (n0-3 / n4-7):
// no predicates, no asm loads -> ptxas batches loads across taps (high MLP);
// 16B lane stride halves L1 wavefronts. Barrier-free, CPB=2, 2-way cin split.

typedef unsigned long long ull;

#define HW 4096
#define PD 66            // padded spatial dim
#define PP (PD * PD)     // 4356
#define SPLIT 2
#define CPB 2

// scratch (allocation-free: __device__ globals)
__device__ float4 g_xp0[32 * PP];              // (cin, 66, 66) n0..3 : 2.2 MB
__device__ float4 g_xp1[32 * PP];              // (cin, 66, 66) n4..7 : 2.2 MB
__device__ float g_part[SPLIT * 8 * 32 * HW];  // partial sums : 8 MB

__device__ __forceinline__ ull pack2(float a, float b) {
    ull r; asm("mov.b64 %0, {%1, %2};" : "=l"(r) : "f"(a), "f"(b)); return r;
}
__device__ __forceinline__ void fma2(ull& d, ull a, ull b) {
    asm("fma.rn.f32x2 %0, %1, %2, %0;" : "+l"(d) : "l"(a), "l"(b));
}
__device__ __forceinline__ float2 unpack2(ull v) {
    float x, y; asm("mov.b64 {%0, %1}, %2;" : "=f"(x), "=f"(y) : "l"(v));
    return make_float2(x, y);
}

// ---- kernel 1: build padded transposed x planes (border = 0) ----
__global__ __launch_bounds__(256) void build_xpad(const float* __restrict__ x) {
    int idx = blockIdx.x * 256 + threadIdx.x;       // < 32 * PP
    if (idx >= 32 * PP) return;
    int cin = idx / PP, rc = idx - cin * PP;
    int hp = rc / PD, wp = rc - hp * PD;            // padded coords
    float4 lo = make_float4(0.f, 0.f, 0.f, 0.f);
    float4 hi = lo;
    int h = hp - 1, w = wp - 1;
    if ((unsigned)h < 64u && (unsigned)w < 64u) {
        int pix = h * 64 + w;
        lo.x = x[(0 * 32 + cin) * HW + pix];
        lo.y = x[(1 * 32 + cin) * HW + pix];
        lo.z = x[(2 * 32 + cin) * HW + pix];
        lo.w = x[(3 * 32 + cin) * HW + pix];
        hi.x = x[(4 * 32 + cin) * HW + pix];
        hi.y = x[(5 * 32 + cin) * HW + pix];
        hi.z = x[(6 * 32 + cin) * HW + pix];
        hi.w = x[(7 * 32 + cin) * HW + pix];
    }
    g_xp0[idx] = lo;
    g_xp1[idx] = hi;
}

// ---- kernel 2: main. block (32,4); warp = 32 consecutive w; no smem/barriers ----
__global__ __launch_bounds__(128, 6) void svconv_main(const float* __restrict__ wt_g) {
    const int lane = threadIdx.x, row = threadIdx.y;
    const int px = blockIdx.x * 32 + lane;
    const int py = blockIdx.y * 4 + row;
    const int c0 = (blockIdx.z & 15) * CPB;        // cout group (2 couts)
    const int s = blockIdx.z >> 4;                 // cin half

    ull acc[CPB][4];
#pragma unroll
    for (int c = 0; c < CPB; c++)
#pragma unroll
        for (int j = 0; j < 4; j++) acc[c][j] = 0ull;

    // padded center pointers for this thread
    const float4* xb0 = g_xp0 + (size_t)(s * 16) * PP + (py + 1) * PD + (px + 1);
    const float4* xb1 = g_xp1 + (size_t)(s * 16) * PP + (py + 1) * PD + (px + 1);
    const float* wp = wt_g + (size_t)(c0 * 32 + s * 16) * 9 * HW + py * 64 + px;

#pragma unroll 1
    for (int ci = 0; ci < 16; ci++) {
#pragma unroll
        for (int t = 0; t < 9; t++) {
            const int off = (t / 3 - 1) * PD + (t % 3 - 1);  // compile-time
            float4 lo = __ldg(xb0 + off);
            float4 hi = __ldg(xb1 + off);
            float wv0 = __ldcs(wp + (size_t)0 * (32 * 9 * HW) + t * HW);
            float wv1 = __ldcs(wp + (size_t)1 * (32 * 9 * HW) + t * HW);
            ull xq0 = pack2(lo.x, lo.y);
            ull xq1 = pack2(lo.z, lo.w);
            ull xq2 = pack2(hi.x, hi.y);
            ull xq3 = pack2(hi.z, hi.w);
            ull wd0 = pack2(wv0, wv0);
            ull wd1 = pack2(wv1, wv1);
            fma2(acc[0][0], wd0, xq0);
            fma2(acc[0][1], wd0, xq1);
            fma2(acc[0][2], wd0, xq2);
            fma2(acc[0][3], wd0, xq3);
            fma2(acc[1][0], wd1, xq0);
            fma2(acc[1][1], wd1, xq1);
            fma2(acc[1][2], wd1, xq2);
            fma2(acc[1][3], wd1, xq3);
        }
        xb0 += PP;           // next cin
        xb1 += PP;
        wp += 9 * HW;
    }

    // write partials (no bias here), coalesced along w
    float* pb = g_part + (size_t)s * (8 * 32 * HW) + (size_t)c0 * HW + py * 64 + px;
#pragma unroll
    for (int c = 0; c < CPB; c++)
#pragma unroll
        for (int j = 0; j < 4; j++) {
            float2 v = unpack2(acc[c][j]);
            int n0 = 2 * j, n1 = 2 * j + 1;
            pb[(((size_t)n0 * 32) + c) * HW] = v.x;
            pb[(((size_t)n1 * 32) + c) * HW] = v.y;
        }
}

// ---- kernel 3: reduce partials + bias ----
__global__ __launch_bounds__(256) void reduce_out(const float* __restrict__ bias,
                                                  float* __restrict__ out) {
    int idx = blockIdx.x * 256 + threadIdx.x;      // < 8*32*4096
    int o = (idx >> 12) & 31;
    out[idx] = g_part[idx] + g_part[idx + 8 * 32 * HW] + bias[o];
}

extern "C" void kernel_launch(void* const* d_in, const int* in_sizes, int n_in,
                              void* d_out, int out_size) {
    const float* x = (const float*)d_in[0];
    const float* wgt = (const float*)d_in[1];
    const float* bias = (const float*)d_in[2];
    float* out = (float*)d_out;

    build_xpad<<<(32 * PP + 255) / 256, 256>>>(x);
    dim3 grid(2, 16, 16 * SPLIT);                  // 1024 blocks
    dim3 block(32, 4);                             // 128 threads
    svconv_main<<<grid, block>>>(wgt);
    reduce_out<<<(8 * 32 * HW) / 256, 256>>>(bias, out);
}